// round 1
// baseline (speedup 1.0000x reference)
#include <cuda_runtime.h>

#define NN 8192
#define PARTS 8
#define IPART (NN / PARTS)      // 1024
#define MTILES 8
#define MTILE 1024
#define LOG2E 1.4426950408889634f

// ---------------- device scratch (no allocations allowed) ----------------
__device__ __align__(16) float4 g_xe[2][NN];           // packed columns of Xe / Se
__device__ unsigned g_maxn2[2];                        // max |xe|^2 per branch (uint-ordered)
__device__ __align__(16) float4 g_pacc[2][PARTS][NN];  // partial weighted sums
__device__ float g_pz[2][PARTS][NN];                   // partial exp sums
__device__ __align__(16) float g_xa[2][4 * NN];        // Xa, Sa row-major (4 x 8192)
__device__ __align__(16) float g_outpart[MTILES][NN * 8];  // GEMV partials

// ---------------- kernel 0: zero atomic-max scratch ----------------
__global__ void k_init() {
    g_maxn2[0] = 0u;
    g_maxn2[1] = 0u;
}

// ---------------- kernel 1: Xe = W1x @ S, Se = W1s @ X, norms ----------------
__global__ void k_prep(const float* __restrict__ X, const float* __restrict__ S,
                       const float* __restrict__ W1x, const float* __restrict__ W1s) {
    int n = blockIdx.x * blockDim.x + threadIdx.x;
    float s0 = S[n], s1 = S[NN + n], s2 = S[2 * NN + n], s3 = S[3 * NN + n];
    float x0 = X[n], x1 = X[NN + n], x2 = X[2 * NN + n], x3 = X[3 * NN + n];

    float4 xe, se;
    xe.x = W1x[0] * s0 + W1x[1] * s1 + W1x[2] * s2 + W1x[3] * s3;
    xe.y = W1x[4] * s0 + W1x[5] * s1 + W1x[6] * s2 + W1x[7] * s3;
    xe.z = W1x[8] * s0 + W1x[9] * s1 + W1x[10] * s2 + W1x[11] * s3;
    xe.w = W1x[12] * s0 + W1x[13] * s1 + W1x[14] * s2 + W1x[15] * s3;
    se.x = W1s[0] * x0 + W1s[1] * x1 + W1s[2] * x2 + W1s[3] * x3;
    se.y = W1s[4] * x0 + W1s[5] * x1 + W1s[6] * x2 + W1s[7] * x3;
    se.z = W1s[8] * x0 + W1s[9] * x1 + W1s[10] * x2 + W1s[11] * x3;
    se.w = W1s[12] * x0 + W1s[13] * x1 + W1s[14] * x2 + W1s[15] * x3;

    g_xe[0][n] = xe;
    g_xe[1][n] = se;

    float nx = xe.x * xe.x + xe.y * xe.y + xe.z * xe.z + xe.w * xe.w;
    float ns = se.x * se.x + se.y * se.y + se.z * se.z + se.w * se.w;
    // nonnegative floats are uint-order-preserving
    atomicMax(&g_maxn2[0], __float_as_uint(nx));
    atomicMax(&g_maxn2[1], __float_as_uint(ns));
}

// ---------------- kernel 2: fused rank-4 attention (single pass, shifted exp) ----------------
// grid = (32 col-tiles, PARTS i-parts, 2 branches), block = 256 (one column per thread)
__global__ __launch_bounds__(256) void k_attn() {
    __shared__ float4 sh[IPART];
    int br = blockIdx.z, part = blockIdx.y;

    const float4* src = g_xe[br] + part * IPART;
    for (int i = threadIdx.x; i < IPART; i += 256) sh[i] = src[i];

    int j = blockIdx.x * 256 + threadIdx.x;
    float4 xj = g_xe[br][j];
    float maxn2 = __uint_as_float(g_maxn2[br]);
    float n2 = xj.x * xj.x + xj.y * xj.y + xj.z * xj.z + xj.w * xj.w;
    // shift M_j = maxnorm*|xe_j| >= max_i s_ij  (Cauchy-Schwarz) -> no max pass needed
    float mneg = -sqrtf(maxn2 * n2) * LOG2E;
    xj.x *= LOG2E; xj.y *= LOG2E; xj.z *= LOG2E; xj.w *= LOG2E;

    __syncthreads();

    float Z = 0.0f;
    float4 acc = make_float4(0.f, 0.f, 0.f, 0.f);
#pragma unroll 4
    for (int i = 0; i < IPART; ++i) {
        float4 xi = sh[i];  // broadcast across warp (all lanes same i)
        float s = fmaf(xi.w, xj.w, mneg);
        s = fmaf(xi.z, xj.z, s);
        s = fmaf(xi.y, xj.y, s);
        s = fmaf(xi.x, xj.x, s);
        float e;
        asm("ex2.approx.ftz.f32 %0, %1;" : "=f"(e) : "f"(s));
        Z += e;
        acc.x = fmaf(e, xi.x, acc.x);
        acc.y = fmaf(e, xi.y, acc.y);
        acc.z = fmaf(e, xi.z, acc.z);
        acc.w = fmaf(e, xi.w, acc.w);
    }
    g_pacc[br][part][j] = acc;
    g_pz[br][part][j] = Z;
}

// ---------------- kernel 3: combine partials -> Xa, Sa (row-major) ----------------
__global__ void k_combine() {
    int idx = blockIdx.x * blockDim.x + threadIdx.x;  // 0..16383
    int br = idx >> 13;
    int j = idx & (NN - 1);
    float4 a = make_float4(0.f, 0.f, 0.f, 0.f);
    float Z = 0.0f;
#pragma unroll
    for (int p = 0; p < PARTS; ++p) {
        float4 t = g_pacc[br][p][j];
        a.x += t.x; a.y += t.y; a.z += t.z; a.w += t.w;
        Z += g_pz[br][p][j];
    }
    float inv = 1.0f / Z;
    g_xa[br][0 * NN + j] = a.x * inv;
    g_xa[br][1 * NN + j] = a.y * inv;
    g_xa[br][2 * NN + j] = a.z * inv;
    g_xa[br][3 * NN + j] = a.w * inv;
}

// ---------------- kernel 4: skinny GEMM  Out[8192][8] = W2 @ [Xa_r | Sa_r] ----------------
// Xa_r[m][c] = Xa[m>>11][4*(m&2047)+c]. grid = (64 k-tiles, MTILES m-tiles), block = 256.
__global__ __launch_bounds__(256) void k_gemv(const float* __restrict__ W2) {
    __shared__ float sh_rhs[8][MTILE];  // c-major -> conflict-free LDS.128
    int mt = blockIdx.y;
    int mbase = mt * MTILE;
    int r = mbase >> 11;         // constant over the whole m-tile (MTILE | 2048)
    int qbase = mbase & 2047;

    for (int mm = threadIdx.x; mm < MTILE; mm += 256) {
        int q = qbase + mm;
        float4 vx = *(const float4*)&g_xa[0][r * NN + 4 * q];
        float4 vs = *(const float4*)&g_xa[1][r * NN + 4 * q];
        sh_rhs[0][mm] = vx.x; sh_rhs[1][mm] = vx.y;
        sh_rhs[2][mm] = vx.z; sh_rhs[3][mm] = vx.w;
        sh_rhs[4][mm] = vs.x; sh_rhs[5][mm] = vs.y;
        sh_rhs[6][mm] = vs.z; sh_rhs[7][mm] = vs.w;
    }
    __syncthreads();

    int warp = threadIdx.x >> 5, lane = threadIdx.x & 31;
    int kbase = blockIdx.x * 128 + warp * 16;

    for (int q4 = 0; q4 < 4; ++q4) {
        int k0 = kbase + q4 * 4;
        float acc[4][8];
#pragma unroll
        for (int rr = 0; rr < 4; ++rr)
#pragma unroll
            for (int c = 0; c < 8; ++c) acc[rr][c] = 0.0f;

        const float* wbase = W2 + (size_t)k0 * NN + mbase + 4 * lane;
#pragma unroll
        for (int u = 0; u < MTILE / 128; ++u) {
            int moff = 128 * u;
            float4 w0 = *(const float4*)(wbase + moff);
            float4 w1 = *(const float4*)(wbase + NN + moff);
            float4 w2v = *(const float4*)(wbase + 2 * NN + moff);
            float4 w3 = *(const float4*)(wbase + 3 * NN + moff);
            int mi = 4 * lane + moff;
#pragma unroll
            for (int c = 0; c < 8; ++c) {
                float4 rc = *(const float4*)&sh_rhs[c][mi];
                acc[0][c] = fmaf(w0.x, rc.x, fmaf(w0.y, rc.y, fmaf(w0.z, rc.z, fmaf(w0.w, rc.w, acc[0][c]))));
                acc[1][c] = fmaf(w1.x, rc.x, fmaf(w1.y, rc.y, fmaf(w1.z, rc.z, fmaf(w1.w, rc.w, acc[1][c]))));
                acc[2][c] = fmaf(w2v.x, rc.x, fmaf(w2v.y, rc.y, fmaf(w2v.z, rc.z, fmaf(w2v.w, rc.w, acc[2][c]))));
                acc[3][c] = fmaf(w3.x, rc.x, fmaf(w3.y, rc.y, fmaf(w3.z, rc.z, fmaf(w3.w, rc.w, acc[3][c]))));
            }
        }
        // butterfly reduce over the 32 m-lanes
#pragma unroll
        for (int rr = 0; rr < 4; ++rr)
#pragma unroll
            for (int c = 0; c < 8; ++c)
#pragma unroll
                for (int off = 16; off; off >>= 1)
                    acc[rr][c] += __shfl_xor_sync(0xffffffffu, acc[rr][c], off);

        if (lane == 0) {
#pragma unroll
            for (int rr = 0; rr < 4; ++rr) {
                float4 a = make_float4(acc[rr][0], acc[rr][1], acc[rr][2], acc[rr][3]);
                float4 b = make_float4(acc[rr][4], acc[rr][5], acc[rr][6], acc[rr][7]);
                *(float4*)&g_outpart[mt][(k0 + rr) * 8] = a;
                *(float4*)&g_outpart[mt][(k0 + rr) * 8 + 4] = b;
            }
        }
    }
}

// ---------------- kernel 5: epilogue — Mx*X, +sin, 3-tap conv (W=1 collapses kw to center) ----------------
__global__ void k_epi(const float* __restrict__ X, const float* __restrict__ S,
                      const float* __restrict__ cwx, const float* __restrict__ cbx,
                      const float* __restrict__ cws, const float* __restrict__ cbs,
                      float* __restrict__ out) {
    __shared__ float swx[8][8][3], sws[8][8][3], sbx[8], sbs[8];
    int tid = threadIdx.x;
    for (int idx = tid; idx < 192; idx += 256) {
        int co = idx / 24, ci = (idx / 3) % 8, kh = idx % 3;
        swx[co][ci][kh] = cwx[((co * 8 + ci) * 3 + kh) * 3 + 1];  // center kw column only
        sws[co][ci][kh] = cws[((co * 8 + ci) * 3 + kh) * 3 + 1];
    }
    if (tid < 8) { sbx[tid] = cbx[tid]; sbs[tid] = cbs[tid]; }
    __syncthreads();

    int h = blockIdx.x * 256 + tid;
    float accX[8], accS[8];
#pragma unroll
    for (int co = 0; co < 8; ++co) { accX[co] = sbx[co]; accS[co] = sbs[co]; }

    for (int kh = 0; kh < 3; ++kh) {
        int hp = h + kh - 1;
        if (hp < 0 || hp >= NN) continue;  // zero padding
        int q = hp >> 2, c = hp & 3;
        float sv_sin = sinf((float)hp);  // sinusoid table, d_hid = B = 1
        float xh[8], sh8[8];
#pragma unroll
        for (int l = 0; l < 4; ++l) {
            float mx = 0.f, ms = 0.f;
            int base = (l * 2048 + q) * 8;
#pragma unroll
            for (int p = 0; p < MTILES; ++p) {
                mx += g_outpart[p][base + c];
                ms += g_outpart[p][base + 4 + c];
            }
            float xv = X[l * NN + hp];
            float svv = S[l * NN + hp];
            xh[l] = mx * xv;            // Xm = Mx * X
            xh[l + 4] = xv;
            sh8[l] = ms * xv + sv_sin;  // Sm = Ms * X (faithful to source), + sin
            sh8[l + 4] = svv + sv_sin;
        }
#pragma unroll
        for (int co = 0; co < 8; ++co) {
            float ax = accX[co], as = accS[co];
#pragma unroll
            for (int ci = 0; ci < 8; ++ci) {
                ax = fmaf(swx[co][ci][kh], xh[ci], ax);
                as = fmaf(sws[co][ci][kh], sh8[ci], as);
            }
            accX[co] = ax; accS[co] = as;
        }
    }
#pragma unroll
    for (int co = 0; co < 8; ++co) {
        out[co * NN + h] = accX[co];            // X_e_hat
        out[(8 + co) * NN + h] = accS[co];      // S_e_hat
    }
}

// ---------------- launch ----------------
extern "C" void kernel_launch(void* const* d_in, const int* in_sizes, int n_in,
                              void* d_out, int out_size) {
    const float* X = (const float*)d_in[0];
    const float* S = (const float*)d_in[1];
    const float* W1x = (const float*)d_in[2];
    const float* W1s = (const float*)d_in[3];
    const float* W2 = (const float*)d_in[4];
    const float* cwx = (const float*)d_in[5];
    const float* cbx = (const float*)d_in[6];
    const float* cws = (const float*)d_in[7];
    const float* cbs = (const float*)d_in[8];
    float* out = (float*)d_out;

    k_init<<<1, 1>>>();
    k_prep<<<NN / 256, 256>>>(X, S, W1x, W1s);
    k_attn<<<dim3(NN / 256, PARTS, 2), 256>>>();
    k_combine<<<(2 * NN) / 256, 256>>>();
    k_gemv<<<dim3(NN / 128, MTILES), 256>>>(W2);
    k_epi<<<NN / 256, 256>>>(X, S, cwx, cbx, cws, cbs, out);
}